// round 3
// baseline (speedup 1.0000x reference)
#include <cuda_runtime.h>
#include <math.h>

#define BB 16
#define NN 4096
#define SS 1024
#define KK 32
#define NPT (BB*SS*KK)      /* 524288 grouped points */
#define NT  (NPT/128)       /* 4096 tiles of 128 points */
#define C1 64
#define C2 64
#define C3 128

// ---------------- scratch (device globals; no runtime allocation) ----------
__device__ float g_newxyz[BB*SS*3];
__device__ __align__(16) float g_buf1[(size_t)NPT*C1];   // [tile][ch64][pt128]
__device__ __align__(16) float g_buf2[(size_t)NPT*C2];   // [tile][ch64][pt128]
__device__ __align__(16) float g_maxpre[BB*SS*C3];       // [q][ch] pre-BN maxima
__device__ float g_p1s[C1*NT], g_p1q[C1*NT];
__device__ float g_p2s[C2*NT], g_p2q[C2*NT];
__device__ float g_p3s[C3*NT], g_p3q[C3*NT];
__device__ float g_sc1[C1], g_sh1[C1];
__device__ float g_sc2[C2], g_sh2[C2];
__device__ float g_sc3[C3], g_sh3[C3];

// ---------------- packed f32x2 helpers (bit-exact: two independent fp32) ---
__device__ __forceinline__ unsigned long long pack2(float lo, float hi) {
    unsigned long long r;
    asm("mov.b64 %0, {%1,%2};" : "=l"(r) : "f"(lo), "f"(hi));
    return r;
}
__device__ __forceinline__ void unpk(unsigned long long v, float& lo, float& hi) {
    asm("mov.b64 {%0,%1}, %2;" : "=f"(lo), "=f"(hi) : "l"(v));
}
__device__ __forceinline__ unsigned long long fma2(unsigned long long a,
                                                   unsigned long long b,
                                                   unsigned long long c) {
    unsigned long long d;
    asm("fma.rn.f32x2 %0, %1, %2, %3;" : "=l"(d) : "l"(a), "l"(b), "l"(c));
    return d;
}
__device__ __forceinline__ unsigned long long add2(unsigned long long a,
                                                   unsigned long long b) {
    unsigned long long d;
    asm("add.rn.f32x2 %0, %1, %2;" : "=l"(d) : "l"(a), "l"(b));
    return d;
}
__device__ __forceinline__ unsigned long long mul2(unsigned long long a,
                                                   unsigned long long b) {
    unsigned long long d;
    asm("mul.rn.f32x2 %0, %1, %2;" : "=l"(d) : "l"(a), "l"(b));
    return d;
}

// ---------------------------------------------------------------------------
// 1) Farthest point sampling. One block per batch. Packed f32x2 distance
//    update (bit-exact), uint-bit argmax, ONE barrier per iteration via
//    double-buffered warp results + redundant all-thread final reduce.
// ---------------------------------------------------------------------------
__global__ __launch_bounds__(256) void fps_kernel(const float* __restrict__ xyz,
                                                  float* __restrict__ out)
{
    const int b = blockIdx.x;
    const int t = threadIdx.x;
    const int T = 256;
    const float* xb = xyz + (size_t)b*3*NN;

    unsigned long long px2[8], py2[8], pz2[8];
    float dist[16];
#pragma unroll
    for (int jp = 0; jp < 8; jp++) {
        int p0 = t + (2*jp)*T;
        int p1 = t + (2*jp+1)*T;
        px2[jp] = pack2(xb[p0],        xb[p1]);
        py2[jp] = pack2(xb[NN + p0],   xb[NN + p1]);
        pz2[jp] = pack2(xb[2*NN + p0], xb[2*NN + p1]);
        dist[2*jp] = 1e10f; dist[2*jp+1] = 1e10f;
    }

    __shared__ unsigned swb[2][8];
    __shared__ int      swi[2][8];
    __shared__ int      sFar[SS];

    const int lane = t & 31;
    const int w    = t >> 5;
    int far = 0;

    for (int i = 0; i < SS; i++) {
        float cx = xb[far];
        float cy = xb[NN + far];
        float cz = xb[2*NN + far];
        if (t == 0) sFar[i] = far;
        unsigned long long ncx = pack2(-cx, -cx);
        unsigned long long ncy = pack2(-cy, -cy);
        unsigned long long ncz = pack2(-cz, -cz);

        unsigned bvb = 0u; int bi = 0;
#pragma unroll
        for (int jp = 0; jp < 8; jp++) {
            unsigned long long dx = add2(px2[jp], ncx);   // == __fsub_rn
            unsigned long long dy = add2(py2[jp], ncy);
            unsigned long long dz = add2(pz2[jp], ncz);
            unsigned long long s  = add2(add2(mul2(dx,dx), mul2(dy,dy)),
                                         mul2(dz,dz));
            float dlo, dhi; unpk(s, dlo, dhi);
            float n0 = fminf(dist[2*jp],   dlo); dist[2*jp]   = n0;
            float n1 = fminf(dist[2*jp+1], dhi); dist[2*jp+1] = n1;
            unsigned b0 = __float_as_uint(n0);
            unsigned b1 = __float_as_uint(n1);
            if (b0 > bvb) { bvb = b0; bi = t + (2*jp)*T; }
            if (b1 > bvb) { bvb = b1; bi = t + (2*jp+1)*T; }
        }
        unsigned wmax = __reduce_max_sync(0xffffffffu, bvb);
        int cand = (bvb == wmax) ? bi : 0x7fffffff;
        int wmin = __reduce_min_sync(0xffffffffu, cand);
        const int par = i & 1;
        if (lane == 0) { swb[par][w] = wmax; swi[par][w] = wmin; }
        __syncthreads();
        unsigned M = swb[par][0]; int fi = swi[par][0];
#pragma unroll
        for (int ww = 1; ww < 8; ww++) {
            unsigned vb = swb[par][ww]; int vi = swi[par][ww];
            if (vb > M || (vb == M && vi < fi)) { M = vb; fi = vi; }
        }
        far = fi;
    }
    __syncthreads();

    // epilogue: write new_xyz + transposed xyz_query output
    for (int i = t; i < SS; i += 256) {
        int f = sFar[i];
        float cx = xb[f], cy = xb[NN + f], cz = xb[2*NN + f];
        g_newxyz[(b*SS + i)*3 + 0] = cx;
        g_newxyz[(b*SS + i)*3 + 1] = cy;
        g_newxyz[(b*SS + i)*3 + 2] = cz;
        out[b*3*SS + 0*SS + i] = cx;
        out[b*3*SS + 1*SS + i] = cy;
        out[b*3*SS + 2*SS + i] = cz;
    }
}

// ---------------------------------------------------------------------------
// 2) FUSED ball query + layer1. Block = 128-pt tile (4 queries), 256 thr.
//    Warps 0-3 do the ball scan for their query into smem; then gather,
//    concat, 6->64 matmul, transposed store + BN partial stats.
// ---------------------------------------------------------------------------
__global__ __launch_bounds__(256) void layer1_kernel(const float* __restrict__ xyz,
                                                     const float* __restrict__ pts,
                                                     const float* __restrict__ W1,
                                                     const float* __restrict__ b1)
{
    const int t = threadIdx.x;
    const int tile = blockIdx.x;
    const int lane = t & 31;
    const int w = t >> 5;

    __shared__ int   sGidx[128];
    __shared__ float sIn[128*6];
    __shared__ float sW[64*8];
    __shared__ float rs[4][64], rq[4][64];

    if (w < 4) {
        // ball query for query q = tile*4 + w
        const int q = tile*4 + w;
        const int bq = q >> 10;
        const float* xb = xyz + (size_t)bq*3*NN;
        const float cx = g_newxyz[q*3 + 0];
        const float cy = g_newxyz[q*3 + 1];
        const float cz = g_newxyz[q*3 + 2];
        const float R2 = 0.16f;
        int cnt = 0;
        int first = 0;
        for (int base = 0; base < NN; base += 32) {
            int p = base + lane;
            float dx = __fsub_rn(xb[p],        cx);
            float dy = __fsub_rn(xb[NN + p],   cy);
            float dz = __fsub_rn(xb[2*NN + p], cz);
            float d  = __fadd_rn(__fadd_rn(__fmul_rn(dx,dx), __fmul_rn(dy,dy)),
                                 __fmul_rn(dz,dz));
            bool in = !(d > R2);
            unsigned mask = __ballot_sync(0xffffffffu, in);
            if (cnt == 0 && mask) first = base + __ffs(mask) - 1;
            if (in) {
                int slot = cnt + __popc(mask & ((1u << lane) - 1u));
                if (slot < KK) sGidx[w*KK + slot] = p;
            }
            cnt += __popc(mask);
            if (cnt >= KK) break;
        }
        if (cnt < KK) {
            for (int slot = cnt + lane; slot < KK; slot += 32)
                sGidx[w*KK + slot] = first;
        }
    } else {
        // warps 4-7 stage the weights
        for (int idx = t - 128; idx < 64*6; idx += 128) {
            int o = idx / 6, c = idx % 6;
            sW[o*8 + c] = W1[o*6 + c];
        }
    }
    __syncthreads();

    // gather + concat
    for (int idx = t; idx < 128*6; idx += 256) {
        int pt = idx / 6, c = idx % 6;
        int q = tile*4 + (pt >> 5);
        int bq = q >> 10;
        int gi = sGidx[pt];
        float v;
        if (c < 3) v = __fsub_rn(xyz[(size_t)bq*3*NN + c*NN + gi], g_newxyz[q*3 + c]);
        else       v = pts[(size_t)bq*3*NN + (c-3)*NN + gi];
        sIn[pt*6 + c] = v;
    }
    __syncthreads();

    const int o  = t & 63;
    const int pg = t >> 6;          // 4 groups of 32 points
    float bo = b1[o];
    float acc[32];
#pragma unroll
    for (int i = 0; i < 32; i++) acc[i] = bo;
#pragma unroll
    for (int c = 0; c < 6; c++) {
        float wv = sW[o*8 + c];
#pragma unroll
        for (int i = 0; i < 32; i++)
            acc[i] = fmaf(sIn[(pg*32 + i)*6 + c], wv, acc[i]);
    }
    float ls = 0.f, lq2 = 0.f;
    float* dst = &g_buf1[(size_t)tile*8192 + o*128 + pg*32];
#pragma unroll
    for (int i4 = 0; i4 < 8; i4++) {
        float4 v4 = make_float4(acc[i4*4+0], acc[i4*4+1], acc[i4*4+2], acc[i4*4+3]);
        ((float4*)dst)[i4] = v4;
        ls  += v4.x + v4.y + v4.z + v4.w;
        lq2 += v4.x*v4.x + v4.y*v4.y + v4.z*v4.z + v4.w*v4.w;
    }
    rs[pg][o] = ls; rq[pg][o] = lq2;
    __syncthreads();
    if (t < 64) {
        g_p1s[t*NT + tile] = rs[0][t] + rs[1][t] + rs[2][t] + rs[3][t];
        g_p1q[t*NT + tile] = rq[0][t] + rq[1][t] + rq[2][t] + rq[3][t];
    }
}

// ---------------------------------------------------------------------------
// Finalize BN stats (double accum), one block per channel, float4 loads.
// ---------------------------------------------------------------------------
__global__ __launch_bounds__(256) void finalize_kernel(const float* __restrict__ gma,
                                                       const float* __restrict__ bet,
                                                       int layer)
{
    const float* ps; const float* pq; float* sc; float* sh;
    if (layer == 0)      { ps = g_p1s; pq = g_p1q; sc = g_sc1; sh = g_sh1; }
    else if (layer == 1) { ps = g_p2s; pq = g_p2q; sc = g_sc2; sh = g_sh2; }
    else                 { ps = g_p3s; pq = g_p3q; sc = g_sc3; sh = g_sh3; }

    const int ch = blockIdx.x, t = threadIdx.x;
    __shared__ double sa[256], sb[256];
    const float4* ps4 = (const float4*)(ps + (size_t)ch*NT);
    const float4* pq4 = (const float4*)(pq + (size_t)ch*NT);
    double a = 0.0, b2 = 0.0;
#pragma unroll
    for (int i = t; i < NT/4; i += 256) {
        float4 v = ps4[i];
        float4 u = pq4[i];
        a  += (double)v.x + (double)v.y + (double)v.z + (double)v.w;
        b2 += (double)u.x + (double)u.y + (double)u.z + (double)u.w;
    }
    sa[t] = a; sb[t] = b2;
    __syncthreads();
    for (int off = 128; off > 0; off >>= 1) {
        if (t < off) { sa[t] += sa[t + off]; sb[t] += sb[t + off]; }
        __syncthreads();
    }
    if (t == 0) {
        const double n = (double)NPT;
        double mean = sa[0] / n;
        double var  = sb[0] / n - mean*mean;
        double s    = (double)gma[ch] / sqrt(var + 1e-5);
        sc[ch] = (float)s;
        sh[ch] = (float)((double)bet[ch] - mean*s);
    }
}

// ---------------------------------------------------------------------------
// 4) Layer2: BN1+ReLU on load, 64->64 matmul, 8x8 register tiles, f32x2 FMA.
// ---------------------------------------------------------------------------
__global__ __launch_bounds__(128, 4) void layer2_kernel(const float* __restrict__ W2,
                                                        const float* __restrict__ b2)
{
    __shared__ __align__(16) float              sInT[32*128];   // [c][pt]
    __shared__ __align__(16) unsigned long long sWT2[32*64];    // [c][ch] dup pairs
    __shared__ float sS[64*16], sQ[64*16];

    const int t = threadIdx.x;
    const int tile = blockIdx.x;
    const int col = t & 15;
    const int row = t >> 4;

    unsigned long long acc[8][4];
#pragma unroll
    for (int j = 0; j < 8; j++) {
        float bo = b2[row*8 + j];
        unsigned long long bp = pack2(bo, bo);
#pragma unroll
        for (int k = 0; k < 4; k++) acc[j][k] = bp;
    }

    const float* src = g_buf1 + (size_t)tile*8192;

    for (int kc = 0; kc < 64; kc += 32) {
        for (int idx = t; idx < 1024; idx += 128) {
            int r = idx >> 5, p4 = idx & 31;
            int c = kc + r;
            float4 v = ((const float4*)(src + c*128))[p4];
            float s = g_sc1[c], h = g_sh1[c];
            float4 o4;
            o4.x = fmaxf(fmaf(v.x, s, h), 0.f);
            o4.y = fmaxf(fmaf(v.y, s, h), 0.f);
            o4.z = fmaxf(fmaf(v.z, s, h), 0.f);
            o4.w = fmaxf(fmaf(v.w, s, h), 0.f);
            ((float4*)(sInT + r*128))[p4] = o4;
        }
        for (int idx = t; idx < 2048; idx += 128) {
            int r = idx >> 6, o = idx & 63;
            float wv = W2[o*64 + kc + r];
            sWT2[r*64 + o] = pack2(wv, wv);
        }
        __syncthreads();
#pragma unroll 4
        for (int c = 0; c < 32; c++) {
            const ulonglong2* pa = (const ulonglong2*)&sInT[c*128 + col*8];
            ulonglong2 a0 = pa[0], a1 = pa[1];
            const ulonglong2* pw = (const ulonglong2*)&sWT2[c*64 + row*8];
            ulonglong2 w0 = pw[0], w1 = pw[1], w2 = pw[2], w3 = pw[3];
            unsigned long long av[4] = { a0.x, a0.y, a1.x, a1.y };
            unsigned long long wv[8] = { w0.x, w0.y, w1.x, w1.y, w2.x, w2.y, w3.x, w3.y };
#pragma unroll
            for (int j = 0; j < 8; j++)
#pragma unroll
                for (int k = 0; k < 4; k++)
                    acc[j][k] = fma2(av[k], wv[j], acc[j][k]);
        }
        __syncthreads();
    }

    float* dst = g_buf2 + (size_t)tile*8192 + col*8;
#pragma unroll
    for (int j = 0; j < 8; j++) {
        int ch = row*8 + j;
        ulonglong2 s0; s0.x = acc[j][0]; s0.y = acc[j][1];
        ulonglong2 s1; s1.x = acc[j][2]; s1.y = acc[j][3];
        ((ulonglong2*)(dst + ch*128))[0] = s0;
        ((ulonglong2*)(dst + ch*128))[1] = s1;
        float ls = 0.f, lq = 0.f;
#pragma unroll
        for (int k = 0; k < 4; k++) {
            float lo, hi; unpk(acc[j][k], lo, hi);
            ls += lo + hi; lq += lo*lo + hi*hi;
        }
        sS[ch*16 + col] = ls; sQ[ch*16 + col] = lq;
    }
    __syncthreads();
    if (t < 64) {
        float s = 0.f, q = 0.f;
#pragma unroll
        for (int cc = 0; cc < 16; cc++) { s += sS[t*16 + cc]; q += sQ[t*16 + cc]; }
        g_p2s[t*NT + tile] = s; g_p2q[t*NT + tile] = q;
    }
}

// ---------------------------------------------------------------------------
// 5) Layer3: BN2+ReLU on load, 64->128 matmul (8x8 tiles, f32x2), stats,
//    fused max-over-k -> g_maxpre.
// ---------------------------------------------------------------------------
__global__ __launch_bounds__(256, 2) void layer3_kernel(const float* __restrict__ W3,
                                                        const float* __restrict__ b3)
{
    __shared__ __align__(16) float              sInT[16*128];
    __shared__ __align__(16) unsigned long long sWT2[16*128];
    __shared__ float sS[128*16], sQ[128*16];

    const int t = threadIdx.x;
    const int tile = blockIdx.x;
    const int col = t & 15;
    const int row = t >> 4;

    unsigned long long acc[8][4];
#pragma unroll
    for (int j = 0; j < 8; j++) {
        float bo = b3[row*8 + j];
        unsigned long long bp = pack2(bo, bo);
#pragma unroll
        for (int k = 0; k < 4; k++) acc[j][k] = bp;
    }

    const float* src = g_buf2 + (size_t)tile*8192;

    for (int kc = 0; kc < 64; kc += 16) {
        for (int idx = t; idx < 512; idx += 256) {
            int r = idx >> 5, p4 = idx & 31;
            int c = kc + r;
            float4 v = ((const float4*)(src + c*128))[p4];
            float s = g_sc2[c], h = g_sh2[c];
            float4 o4;
            o4.x = fmaxf(fmaf(v.x, s, h), 0.f);
            o4.y = fmaxf(fmaf(v.y, s, h), 0.f);
            o4.z = fmaxf(fmaf(v.z, s, h), 0.f);
            o4.w = fmaxf(fmaf(v.w, s, h), 0.f);
            ((float4*)(sInT + r*128))[p4] = o4;
        }
        for (int idx = t; idx < 2048; idx += 256) {
            int r = idx >> 7, o = idx & 127;
            float wv = W3[o*64 + kc + r];
            sWT2[r*128 + o] = pack2(wv, wv);
        }
        __syncthreads();
#pragma unroll 4
        for (int c = 0; c < 16; c++) {
            const ulonglong2* pa = (const ulonglong2*)&sInT[c*128 + col*8];
            ulonglong2 a0 = pa[0], a1 = pa[1];
            const ulonglong2* pw = (const ulonglong2*)&sWT2[c*128 + row*8];
            ulonglong2 w0 = pw[0], w1 = pw[1], w2 = pw[2], w3 = pw[3];
            unsigned long long av[4] = { a0.x, a0.y, a1.x, a1.y };
            unsigned long long wv[8] = { w0.x, w0.y, w1.x, w1.y, w2.x, w2.y, w3.x, w3.y };
#pragma unroll
            for (int j = 0; j < 8; j++)
#pragma unroll
                for (int k = 0; k < 4; k++)
                    acc[j][k] = fma2(av[k], wv[j], acc[j][k]);
        }
        __syncthreads();
    }

#pragma unroll
    for (int j = 0; j < 8; j++) {
        int ch = row*8 + j;
        float ls = 0.f, lq = 0.f;
#pragma unroll
        for (int k = 0; k < 4; k++) {
            float lo, hi; unpk(acc[j][k], lo, hi);
            ls += lo + hi; lq += lo*lo + hi*hi;
        }
        sS[ch*16 + col] = ls; sQ[ch*16 + col] = lq;
    }
    __syncthreads();
    if (t < 128) {
        float s = 0.f, q = 0.f;
#pragma unroll
        for (int cc = 0; cc < 16; cc++) { s += sS[t*16 + cc]; q += sQ[t*16 + cc]; }
        g_p3s[t*NT + tile] = s; g_p3q[t*NT + tile] = q;
    }
    __syncthreads();

#pragma unroll
    for (int j = 0; j < 8; j++) {
        int ch = row*8 + j;
        float m = -3.0e38f;
#pragma unroll
        for (int k = 0; k < 4; k++) {
            float lo, hi; unpk(acc[j][k], lo, hi);
            m = fmaxf(m, fmaxf(lo, hi));
        }
        sS[ch*16 + col] = m;
    }
    __syncthreads();
    if (t < 128) {
#pragma unroll
        for (int qq = 0; qq < 4; qq++) {
            float m = sS[t*16 + qq*4 + 0];
            m = fmaxf(m, sS[t*16 + qq*4 + 1]);
            m = fmaxf(m, sS[t*16 + qq*4 + 2]);
            m = fmaxf(m, sS[t*16 + qq*4 + 3]);
            g_maxpre[(size_t)((tile<<2) + qq)*128 + t] = m;
        }
    }
}

// ---------------------------------------------------------------------------
// 6) Final: BN3+ReLU on per-query maxima (scale>0: max commutes exactly).
// ---------------------------------------------------------------------------
__global__ __launch_bounds__(256) void maxfinal_kernel(float* __restrict__ out)
{
    const int gid = blockIdx.x * 256 + threadIdx.x;
    const int s = gid & 1023;
    const int rest = gid >> 10;
    const int o = rest & 127;
    const int b = rest >> 7;
    const int q = b*1024 + s;
    float v = g_maxpre[(size_t)q*128 + o];
    float r = fmaxf(fmaf(v, g_sc3[o], g_sh3[o]), 0.f);
    out[BB*3*SS + (size_t)b*C3*SS + o*SS + s] = r;
}

// ---------------------------------------------------------------------------
extern "C" void kernel_launch(void* const* d_in, const int* in_sizes, int n_in,
                              void* d_out, int out_size)
{
    const float* xyz = (const float*)d_in[0];
    const float* pts = (const float*)d_in[1];
    const float* W1  = (const float*)d_in[2];
    const float* b1  = (const float*)d_in[3];
    const float* g1  = (const float*)d_in[4];
    const float* be1 = (const float*)d_in[5];
    const float* W2  = (const float*)d_in[6];
    const float* b2  = (const float*)d_in[7];
    const float* g2  = (const float*)d_in[8];
    const float* be2 = (const float*)d_in[9];
    const float* W3  = (const float*)d_in[10];
    const float* b3  = (const float*)d_in[11];
    const float* g3  = (const float*)d_in[12];
    const float* be3 = (const float*)d_in[13];
    float* out = (float*)d_out;

    fps_kernel<<<BB, 256>>>(xyz, out);                 // 0
    layer1_kernel<<<NT, 256>>>(xyz, pts, W1, b1);      // 1 (fused ball query)
    finalize_kernel<<<C1, 256>>>(g1, be1, 0);          // 2
    layer2_kernel<<<NT, 128>>>(W2, b2);                // 3
    finalize_kernel<<<C2, 256>>>(g2, be2, 1);          // 4
    layer3_kernel<<<NT, 256>>>(W3, b3);                // 5  <- ncu -s 5 target
    finalize_kernel<<<C3, 256>>>(g3, be3, 2);          // 6
    maxfinal_kernel<<<(BB*SS*C3)/256, 256>>>(out);     // 7
}